// round 17
// baseline (speedup 1.0000x reference)
#include <cuda_runtime.h>
#include <cuda_bf16.h>
#include <cstdint>

// Problem constants (B=256, S=1024, H=128)
#define SEQ   1024
#define HID   128
#define NB    2              // batches per CTA (n-cols 0,1 of the n8 tile)
#define NCTA  128            // 1 CTA per SM (single wave on 148 SMs)
#define NTHR  256            // 8 warps; warp w owns UNITS [16w,16w+16), all 3 gates
#define HPAD  136            // bf16 elements per h row (+8 pad -> conflict-free)

// Single-MUFU transcendentals (sm_75+ tanh unit)
__device__ __forceinline__ float tanha(float x) {
    float y;
    asm("tanh.approx.f32 %0, %1;" : "=f"(y) : "f"(x));
    return y;
}
__device__ __forceinline__ float fsig(float s) {   // sigma(s)=0.5*tanh(s/2)+0.5
    return fmaf(tanha(s * 0.5f), 0.5f, 0.5f);
}

__global__ void __launch_bounds__(NTHR, 1)
gru_fused_kernel(const float* __restrict__ x,     // [B, S]
                 const float* __restrict__ w_ih,  // [3H]
                 const float* __restrict__ w_hh,  // [3H, H]
                 const float* __restrict__ b_ih,  // [3H]
                 const float* __restrict__ b_hh,  // [3H]
                 const float* __restrict__ w_fc,  // [H]
                 const float* __restrict__ b_fc,  // [1]
                 float* __restrict__ out)         // [B]
{
    __shared__ __align__(16) float x_sh[NB][SEQ];               // 8 KB
    __shared__ __align__(16) __nv_bfloat16 h_sh[2][8][HPAD];    // double-buffered B
    __shared__ __align__(16) float red_sh[NB][HID];             // fc scratch

    const int t    = threadIdx.x;
    const int b0   = blockIdx.x * NB;
    const int w    = t >> 5;
    const int lane = t & 31;
    const int g    = lane >> 2;      // row-in-tile (0..7)
    const int tg   = lane & 3;       // k-subgroup

    // ---- A fragments, GATE-MAJOR permutation ----
    // m-tile mt = gate; warp w's tile rows = units [16w,16w+16) of gate mt.
    // W_hh row for (mt, unit r) = mt*128 + r.  3 x 8 x 4 = 96 regs.
    uint32_t a_[3][8][4];
    #pragma unroll
    for (int mt = 0; mt < 3; mt++) {
        const int r0 = mt * HID + w * 16 + g;     // unit 16w+g, gate mt
        #pragma unroll
        for (int kc = 0; kc < 8; kc++) {
            const float* p0 = w_hh + r0 * HID + kc * 16 + 2 * tg;
            const float* p1 = p0 + 8 * HID;       // unit +8, same gate
            float2 v; __nv_bfloat162 q;
            v = *(const float2*)(p0);
            q = __floats2bfloat162_rn(v.x, v.y); a_[mt][kc][0] = *(uint32_t*)&q;
            v = *(const float2*)(p1);
            q = __floats2bfloat162_rn(v.x, v.y); a_[mt][kc][1] = *(uint32_t*)&q;
            v = *(const float2*)(p0 + 8);
            q = __floats2bfloat162_rn(v.x, v.y); a_[mt][kc][2] = *(uint32_t*)&q;
            v = *(const float2*)(p1 + 8);
            q = __floats2bfloat162_rn(v.x, v.y); a_[mt][kc][3] = *(uint32_t*)&q;
        }
    }

    // ---- gate constants for the 2 units this (tg==0) lane finalizes ----
    const int u1 = w * 16 + g;
    const int u2 = u1 + 8;
    const float Ar1 = w_ih[u1],           Ar2 = w_ih[u2];
    const float Az1 = w_ih[HID + u1],     Az2 = w_ih[HID + u2];
    const float An1 = w_ih[2*HID + u1],   An2 = w_ih[2*HID + u2];
    const float Cr1 = b_ih[u1] + b_hh[u1],            Cr2 = b_ih[u2] + b_hh[u2];
    const float Cz1 = b_ih[HID+u1] + b_hh[HID+u1],    Cz2 = b_ih[HID+u2] + b_hh[HID+u2];
    const float Cni1 = b_ih[2*HID+u1],    Cni2 = b_ih[2*HID+u2];
    const float Cnh1 = b_hh[2*HID+u1],    Cnh2 = b_hh[2*HID+u2];
    float h00 = 0.f, h01 = 0.f, h10 = 0.f, h11 = 0.f;  // (u1,b0)(u1,b1)(u2,b0)(u2,b1)

    // ---- stage x; zero BOTH h buffers (rows 2..7 stay zero forever) ----
    {
        const float4* xg = reinterpret_cast<const float4*>(x + b0 * SEQ);
        float4* xs = reinterpret_cast<float4*>(&x_sh[0][0]);
        for (int i = t; i < NB * SEQ / 4; i += NTHR)
            xs[i] = xg[i];
    }
    for (int i = t; i < 2 * 8 * HPAD; i += NTHR)
        (&h_sh[0][0][0])[i] = __float2bfloat16(0.0f);
    __syncthreads();

    for (int s = 0; s < SEQ; s++) {
        const int rb = s & 1;

        // ===== tensor matvec: D[3x128 x 8] = Wperm @ h[128x8] =====
        float c0_[3], c1_[3], c2_[3], c3_[3];
        #pragma unroll
        for (int mt = 0; mt < 3; mt++) {
            c0_[mt] = 0.f; c1_[mt] = 0.f; c2_[mt] = 0.f; c3_[mt] = 0.f;
        }
        #pragma unroll
        for (int kc = 0; kc < 8; kc++) {
            uint32_t br0 = *(const uint32_t*)&h_sh[rb][g][kc * 16 + 2 * tg];
            uint32_t br1 = *(const uint32_t*)&h_sh[rb][g][kc * 16 + 2 * tg + 8];
            #pragma unroll
            for (int mt = 0; mt < 3; mt++) {
                asm volatile(
                    "mma.sync.aligned.m16n8k16.row.col.f32.bf16.bf16.f32 "
                    "{%0,%1,%2,%3}, {%4,%5,%6,%7}, {%8,%9}, {%0,%1,%2,%3};"
                    : "+f"(c0_[mt]), "+f"(c1_[mt]), "+f"(c2_[mt]), "+f"(c3_[mt])
                    : "r"(a_[mt][kc][0]), "r"(a_[mt][kc][1]),
                      "r"(a_[mt][kc][2]), "r"(a_[mt][kc][3]),
                      "r"(br0), "r"(br1));
            }
        }

        // ===== gates, fully in-register on tg==0 lanes =====
        // c0_[mt]=D[gate mt][u1][b0], c1_=b1; c2_/c3_ = u2.
        if (tg == 0) {
            float xv0 = x_sh[0][s];
            float xv1 = x_sh[1][s];
            // (u1,b0)
            float r, z, n;
            r = fsig(fmaf(xv0, Ar1, Cr1) + c0_[0]);
            z = fsig(fmaf(xv0, Az1, Cz1) + c0_[1]);
            n = tanha(fmaf(xv0, An1, Cni1) + r * (c0_[2] + Cnh1));
            h00 = n + z * (h00 - n);
            // (u1,b1)
            r = fsig(fmaf(xv1, Ar1, Cr1) + c1_[0]);
            z = fsig(fmaf(xv1, Az1, Cz1) + c1_[1]);
            n = tanha(fmaf(xv1, An1, Cni1) + r * (c1_[2] + Cnh1));
            h01 = n + z * (h01 - n);
            // (u2,b0)
            r = fsig(fmaf(xv0, Ar2, Cr2) + c2_[0]);
            z = fsig(fmaf(xv0, Az2, Cz2) + c2_[1]);
            n = tanha(fmaf(xv0, An2, Cni2) + r * (c2_[2] + Cnh2));
            h10 = n + z * (h10 - n);
            // (u2,b1)
            r = fsig(fmaf(xv1, Ar2, Cr2) + c3_[0]);
            z = fsig(fmaf(xv1, Az2, Cz2) + c3_[1]);
            n = tanha(fmaf(xv1, An2, Cni2) + r * (c3_[2] + Cnh2));
            h11 = n + z * (h11 - n);
            // write NEXT buffer's B tile
            h_sh[rb ^ 1][0][u1] = __float2bfloat16(h00);
            h_sh[rb ^ 1][1][u1] = __float2bfloat16(h01);
            h_sh[rb ^ 1][0][u2] = __float2bfloat16(h10);
            h_sh[rb ^ 1][1][u2] = __float2bfloat16(h11);
        }
        __syncthreads();   // single barrier per step (double-buffered h)
    }

    // ---- fused fc1: out[b] = relu(hT) . w_fc + b_fc ----
    if (tg == 0) {
        float wf1 = w_fc[u1], wf2 = w_fc[u2];
        red_sh[0][u1] = fmaxf(h00, 0.f) * wf1;
        red_sh[1][u1] = fmaxf(h01, 0.f) * wf1;
        red_sh[0][u2] = fmaxf(h10, 0.f) * wf2;
        red_sh[1][u2] = fmaxf(h11, 0.f) * wf2;
    }
    __syncthreads();
    if (w < NB) {
        float acc = red_sh[w][lane] + red_sh[w][lane + 32] +
                    red_sh[w][lane + 64] + red_sh[w][lane + 96];
        #pragma unroll
        for (int off = 16; off; off >>= 1)
            acc += __shfl_xor_sync(0xffffffffu, acc, off);
        if (lane == 0)
            out[b0 + w] = acc + b_fc[0];
    }
}

extern "C" void kernel_launch(void* const* d_in, const int* in_sizes, int n_in,
                              void* d_out, int out_size) {
    const float* x    = (const float*)d_in[0];
    const float* w_ih = (const float*)d_in[1];
    const float* w_hh = (const float*)d_in[2];
    const float* b_ih = (const float*)d_in[3];
    const float* b_hh = (const float*)d_in[4];
    const float* w_fc = (const float*)d_in[5];
    const float* b_fc = (const float*)d_in[6];
    float* out = (float*)d_out;

    gru_fused_kernel<<<NCTA, NTHR>>>(x, w_ih, w_hh, b_ih, b_hh, w_fc, b_fc, out);
}